// round 2
// baseline (speedup 1.0000x reference)
#include <cuda_runtime.h>
#include <math.h>

#define NS 25
#define NQT 100
#define NB 125
#define SEQ 8
#define DIN 2048
#define DOUT 1152
#define TT 56
#define WAY 5
#define MPAD 1024      // padded rows for X/Y (125*8 = 1000)
#define QROWS 5600     // 100*56
#define QPAD 5632      // 44*128
#define CROWS 280      // 5*56
#define CPAD 288       // padded, multiple of 8

// ---------------- scratch (static device globals; no allocs) ----------------
__device__ float Xf[2][MPAD][DIN];        // per-stream position features (+PE)
__device__ float Yf[12][MPAD][DOUT];      // (stream*6 + wtype*3 + j) position projections
__device__ float QKm[2][QPAD][DOUT];      // query keys (LN'd), per stream
__device__ float CKb[10][CPAD][DOUT];     // class keys   [stream*5+c][shot*56+t]
__device__ float CVb[10][CPAD][DOUT];     // class values
__device__ float QVm[QPAD][2 * DOUT];     // query values, concat streams
__device__ float Sb[10][QPAD][CPAD];      // attention scores / probs
__device__ float Dq[WAY][QPAD];           // per (class,row) partial distances

__constant__ int TUP[56][3] = {
  {0,1,2},{0,1,3},{0,1,4},{0,1,5},{0,1,6},{0,1,7},
  {0,2,3},{0,2,4},{0,2,5},{0,2,6},{0,2,7},
  {0,3,4},{0,3,5},{0,3,6},{0,3,7},
  {0,4,5},{0,4,6},{0,4,7},
  {0,5,6},{0,5,7},
  {0,6,7},
  {1,2,3},{1,2,4},{1,2,5},{1,2,6},{1,2,7},
  {1,3,4},{1,3,5},{1,3,6},{1,3,7},
  {1,4,5},{1,4,6},{1,4,7},
  {1,5,6},{1,5,7},
  {1,6,7},
  {2,3,4},{2,3,5},{2,3,6},{2,3,7},
  {2,4,5},{2,4,6},{2,4,7},
  {2,5,6},{2,5,7},
  {2,6,7},
  {3,4,5},{3,4,6},{3,4,7},
  {3,5,6},{3,5,7},
  {3,6,7},
  {4,5,6},{4,5,7},
  {4,6,7},
  {5,6,7}
};

// ---------------- zero pads + distance accumulators ----------------
// region sizes
#define Z0 (WAY*QPAD)          // Dq
#define Z1 (2*24*DIN)          // Xf pad rows 1000..1023
#define Z2 (2*32*DOUT)         // QK pad rows 5600..5631
#define Z3 (10*8*DOUT)         // CK pad rows 280..287
#define Z4 (10*8*DOUT)         // CV pad rows
__global__ void zero_kernel() {
    int idx = blockIdx.x * 256 + threadIdx.x;
    if (idx < Z0) { ((float*)Dq)[idx] = 0.f; return; }
    idx -= Z0;
    if (idx < Z1) {
        int s = idx / (24 * DIN); int r = idx % (24 * DIN);
        Xf[s][1000 + r / DIN][r % DIN] = 0.f; return;
    }
    idx -= Z1;
    if (idx < Z2) {
        int s = idx / (32 * DOUT); int r = idx % (32 * DOUT);
        QKm[s][QROWS + r / DOUT][r % DOUT] = 0.f; return;
    }
    idx -= Z2;
    if (idx < Z3) {
        int z = idx / (8 * DOUT); int r = idx % (8 * DOUT);
        CKb[z][CROWS + r / DOUT][r % DOUT] = 0.f; return;
    }
    idx -= Z3;
    if (idx < Z4) {
        int z = idx / (8 * DOUT); int r = idx % (8 * DOUT);
        CVb[z][CROWS + r / DOUT][r % DOUT] = 0.f; return;
    }
}

// ---------------- prep: add PE, split streams ----------------
__global__ void prep_kernel(const float* __restrict__ sup, const float* __restrict__ qry) {
    int idx = blockIdx.x * 256 + threadIdx.x;   // 0 .. 1000*2048-1
    int r = idx >> 11, c = idx & 2047;
    int i = r >> 3, p = r & 7;
    const float* base = (i < NS) ? sup + (size_t)(i * 8 + p) * (2 * DIN)
                                 : qry + (size_t)((i - NS) * 8 + p) * (2 * DIN);
    int h = c >> 1;
    float div = expf((float)(2 * h) * (-logf(10000.0f) / (float)DIN));
    float ang = (float)p * div;
    float pe = ((c & 1) ? cosf(ang) : sinf(ang)) * 0.1f;
    Xf[0][r][c] = base[c] + pe;
    Xf[1][r][c] = base[DIN + c] + pe;
}

// ---------------- projection GEMM: Y[z] = X[stream] @ Wblk ----------------
// z = stream*6 + wtype*3 + j.  M=1024, N=1152, K=2048, no guards needed.
__global__ void __launch_bounds__(256) gemm_proj(
    const float* __restrict__ Wk, const float* __restrict__ Wv,
    const float* __restrict__ Wkl, const float* __restrict__ Wvl)
{
    int z = blockIdx.z;
    int stream = z / 6, wt = (z % 6) / 3, j = z % 3;
    const float* Wmat = stream ? (wt ? Wvl : Wkl) : (wt ? Wv : Wk);
    const float* A = &Xf[stream][0][0];
    const float* B = Wmat + (size_t)j * DIN * DOUT;
    float* C = &Yf[z][0][0];

    __shared__ float As[8][128];
    __shared__ float Bs[8][128];
    int tid = threadIdx.x;
    int tx = tid & 15, ty = tid >> 4;
    int row0 = blockIdx.y * 128, col0 = blockIdx.x * 128;
    int arow = tid >> 1, ac4 = (tid & 1) * 4;
    int brow = tid >> 5, bc4 = (tid & 31) * 4;
    float acc[8][8];
#pragma unroll
    for (int ii = 0; ii < 8; ii++)
#pragma unroll
        for (int jj = 0; jj < 8; jj++) acc[ii][jj] = 0.f;

    for (int k0 = 0; k0 < DIN; k0 += 8) {
        float4 av = *(const float4*)&A[(size_t)(row0 + arow) * DIN + k0 + ac4];
        As[ac4 + 0][arow] = av.x; As[ac4 + 1][arow] = av.y;
        As[ac4 + 2][arow] = av.z; As[ac4 + 3][arow] = av.w;
        *(float4*)&Bs[brow][bc4] = *(const float4*)&B[(size_t)(k0 + brow) * DOUT + col0 + bc4];
        __syncthreads();
#pragma unroll
        for (int kk = 0; kk < 8; kk++) {
            float a[8], b[8];
            *(float4*)&a[0] = *(float4*)&As[kk][ty * 8];
            *(float4*)&a[4] = *(float4*)&As[kk][ty * 8 + 4];
            *(float4*)&b[0] = *(float4*)&Bs[kk][tx * 8];
            *(float4*)&b[4] = *(float4*)&Bs[kk][tx * 8 + 4];
#pragma unroll
            for (int ii = 0; ii < 8; ii++)
#pragma unroll
                for (int jj = 0; jj < 8; jj++) acc[ii][jj] += a[ii] * b[jj];
        }
        __syncthreads();
    }
#pragma unroll
    for (int ii = 0; ii < 8; ii++) {
        float* cp = &C[(size_t)(row0 + ty * 8 + ii) * DOUT + col0 + tx * 8];
        *(float4*)&cp[0] = *(float4*)&acc[ii][0];
        *(float4*)&cp[4] = *(float4*)&acc[ii][4];
    }
}

// ---------------- combine: gather 3 position projections + bias (+LN for K) ----------------
__global__ void combine_kernel(
    const float* __restrict__ bk, const float* __restrict__ bv,
    const float* __restrict__ bkl, const float* __restrict__ bvl,
    const float* __restrict__ lng, const float* __restrict__ lnb,
    const int* __restrict__ labels)
{
    int bt = blockIdx.x;           // 0..6999
    int i = bt / TT, t = bt % TT;
    int mat = blockIdx.y;          // 0=Kg 1=Vg 2=Kl 3=Vl
    int stream = mat >> 1, wt = mat & 1;
    int p0 = TUP[t][0], p1 = TUP[t][1], p2 = TUP[t][2];
    const float* Y0 = &Yf[stream * 6 + wt * 3 + 0][i * 8 + p0][0];
    const float* Y1 = &Yf[stream * 6 + wt * 3 + 1][i * 8 + p1][0];
    const float* Y2 = &Yf[stream * 6 + wt * 3 + 2][i * 8 + p2][0];
    const float* bias = stream ? (wt ? bvl : bkl) : (wt ? bv : bk);

    int tid = threadIdx.x;  // 128
    float v[9];
    float s1 = 0.f, s2 = 0.f;
#pragma unroll
    for (int w = 0; w < 9; w++) {
        int u = tid + w * 128;
        float val = Y0[u] + Y1[u] + Y2[u] + bias[u];
        v[w] = val; s1 += val; s2 += val * val;
    }

    float* dst;
    if (i >= NS) {
        int q = i - NS;
        if (wt == 0) dst = &QKm[stream][q * TT + t][0];
        else         dst = &QVm[q * TT + t][stream * DOUT];
    } else {
        int c = labels[i];
        int shot = 0;
        for (int j2 = 0; j2 < i; j2++) if (labels[j2] == c) shot++;
        int cs = stream * 5 + c;
        int row = shot * TT + t;
        dst = wt ? &CVb[cs][row][0] : &CKb[cs][row][0];
    }

    if (wt == 0) {
        __shared__ float red1[4], red2[4];
        __shared__ float stats[2];
        int lane = tid & 31, wid = tid >> 5;
#pragma unroll
        for (int off = 16; off; off >>= 1) {
            s1 += __shfl_down_sync(0xFFFFFFFFu, s1, off);
            s2 += __shfl_down_sync(0xFFFFFFFFu, s2, off);
        }
        if (lane == 0) { red1[wid] = s1; red2[wid] = s2; }
        __syncthreads();
        if (tid == 0) {
            float a = red1[0] + red1[1] + red1[2] + red1[3];
            float b = red2[0] + red2[1] + red2[2] + red2[3];
            float mean = a / (float)DOUT;
            float var = b / (float)DOUT - mean * mean;
            stats[0] = mean;
            stats[1] = rsqrtf(var + 1e-5f);
        }
        __syncthreads();
        float mean = stats[0], inv = stats[1];
#pragma unroll
        for (int w = 0; w < 9; w++) {
            int u = tid + w * 128;
            dst[u] = (v[w] - mean) * inv * lng[u] + lnb[u];
        }
    } else {
#pragma unroll
        for (int w = 0; w < 9; w++) {
            int u = tid + w * 128;
            dst[u] = v[w];
        }
    }
}

// ---------------- scores GEMM: S[z] = QK[stream] @ CK[z]^T ----------------
// M=5632, N=280(pad 288, tiles cover 384 w/ guards), K=1152.
__global__ void __launch_bounds__(256) gemm_scores() {
    int z = blockIdx.z;                 // cs = stream*5 + c
    const float* A = &QKm[z / 5][0][0];
    const float* Bc = &CKb[z][0][0];    // (CPAD x 1152); B(k,n) = Bc[n*1152+k]
    float* C = &Sb[z][0][0];

    __shared__ float As[8][128];
    __shared__ float Bs[8][128];
    int tid = threadIdx.x;
    int tx = tid & 15, ty = tid >> 4;
    int row0 = blockIdx.y * 128, col0 = blockIdx.x * 128;
    int arow = tid >> 1, ac4 = (tid & 1) * 4;
    int nl = tid >> 1, kq = (tid & 1) * 4;
    float acc[8][8];
#pragma unroll
    for (int ii = 0; ii < 8; ii++)
#pragma unroll
        for (int jj = 0; jj < 8; jj++) acc[ii][jj] = 0.f;

    for (int k0 = 0; k0 < DOUT; k0 += 8) {
        float4 av = *(const float4*)&A[(size_t)(row0 + arow) * DOUT + k0 + ac4];
        As[ac4 + 0][arow] = av.x; As[ac4 + 1][arow] = av.y;
        As[ac4 + 2][arow] = av.z; As[ac4 + 3][arow] = av.w;
        int ng = col0 + nl;
        float4 bv = make_float4(0.f, 0.f, 0.f, 0.f);
        if (ng < CROWS) bv = *(const float4*)&Bc[(size_t)ng * DOUT + k0 + kq];
        Bs[kq + 0][nl] = bv.x; Bs[kq + 1][nl] = bv.y;
        Bs[kq + 2][nl] = bv.z; Bs[kq + 3][nl] = bv.w;
        __syncthreads();
#pragma unroll
        for (int kk = 0; kk < 8; kk++) {
            float a[8], b[8];
            *(float4*)&a[0] = *(float4*)&As[kk][ty * 8];
            *(float4*)&a[4] = *(float4*)&As[kk][ty * 8 + 4];
            *(float4*)&b[0] = *(float4*)&Bs[kk][tx * 8];
            *(float4*)&b[4] = *(float4*)&Bs[kk][tx * 8 + 4];
#pragma unroll
            for (int ii = 0; ii < 8; ii++)
#pragma unroll
                for (int jj = 0; jj < 8; jj++) acc[ii][jj] += a[ii] * b[jj];
        }
        __syncthreads();
    }
    if (col0 + tx * 8 < CPAD) {
#pragma unroll
        for (int ii = 0; ii < 8; ii++) {
            float* cp = &C[(size_t)(row0 + ty * 8 + ii) * CPAD + col0 + tx * 8];
            *(float4*)&cp[0] = *(float4*)&acc[ii][0];
            *(float4*)&cp[4] = *(float4*)&acc[ii][4];
        }
    }
}

// ---------------- softmax: warp per row over 280 cols ----------------
__global__ void softmax_kernel() {
    int rowid = blockIdx.x * 8 + (threadIdx.x >> 5);  // 0..55999
    int lane = threadIdx.x & 31;
    int z = rowid / QROWS, r = rowid % QROWS;
    float* p = &Sb[z][r][0];
    const float scale = 1.0f / sqrtf((float)DOUT);
    float vals[9];
    float mx = -1e30f;
#pragma unroll
    for (int k = 0; k < 9; k++) {
        int cix = lane + 32 * k;
        float x = (cix < CROWS) ? p[cix] * scale : -1e30f;
        vals[k] = x; mx = fmaxf(mx, x);
    }
#pragma unroll
    for (int off = 16; off; off >>= 1) mx = fmaxf(mx, __shfl_xor_sync(0xFFFFFFFFu, mx, off));
    float sum = 0.f;
#pragma unroll
    for (int k = 0; k < 9; k++) {
        int cix = lane + 32 * k;
        if (cix < CROWS) { vals[k] = expf(vals[k] - mx); sum += vals[k]; }
    }
#pragma unroll
    for (int off = 16; off; off >>= 1) sum += __shfl_xor_sync(0xFFFFFFFFu, sum, off);
    float inv = 1.0f / sum;
#pragma unroll
    for (int k = 0; k < 9; k++) {
        int cix = lane + 32 * k;
        if (cix < CROWS) p[cix] = vals[k] * inv;
    }
}

// ---------------- AV GEMM + fused distance epilogue ----------------
// proto = S[z] @ CV[z]; accumulate (qv - proto)^2 into Dq[c][row].
__global__ void __launch_bounds__(256) gemm_av() {
    int z = blockIdx.z;
    int c = z % 5, stream = z / 5;
    const float* A = &Sb[z][0][0];     // 5632 x 288
    const float* B = &CVb[z][0][0];    // 288 x 1152

    __shared__ float As[8][128];
    __shared__ float Bs[8][128];
    int tid = threadIdx.x;
    int tx = tid & 15, ty = tid >> 4;
    int row0 = blockIdx.y * 128, col0 = blockIdx.x * 128;
    int arow = tid >> 1, ac4 = (tid & 1) * 4;
    int brow = tid >> 5, bc4 = (tid & 31) * 4;
    float acc[8][8];
#pragma unroll
    for (int ii = 0; ii < 8; ii++)
#pragma unroll
        for (int jj = 0; jj < 8; jj++) acc[ii][jj] = 0.f;

    for (int k0 = 0; k0 < CPAD; k0 += 8) {
        float4 av = *(const float4*)&A[(size_t)(row0 + arow) * CPAD + k0 + ac4];
        As[ac4 + 0][arow] = av.x; As[ac4 + 1][arow] = av.y;
        As[ac4 + 2][arow] = av.z; As[ac4 + 3][arow] = av.w;
        *(float4*)&Bs[brow][bc4] = *(const float4*)&B[(size_t)(k0 + brow) * DOUT + col0 + bc4];
        __syncthreads();
#pragma unroll
        for (int kk = 0; kk < 8; kk++) {
            float a[8], b[8];
            *(float4*)&a[0] = *(float4*)&As[kk][ty * 8];
            *(float4*)&a[4] = *(float4*)&As[kk][ty * 8 + 4];
            *(float4*)&b[0] = *(float4*)&Bs[kk][tx * 8];
            *(float4*)&b[4] = *(float4*)&Bs[kk][tx * 8 + 4];
#pragma unroll
            for (int ii = 0; ii < 8; ii++)
#pragma unroll
                for (int jj = 0; jj < 8; jj++) acc[ii][jj] += a[ii] * b[jj];
        }
        __syncthreads();
    }

    // fused distance: sum over cols of (qv - proto)^2 per row
    __shared__ float part[128][17];
#pragma unroll
    for (int ii = 0; ii < 8; ii++) {
        int rg = row0 + ty * 8 + ii;
        float s = 0.f;
        if (rg < QROWS) {
            float qa[8];
            const float* qp = &QVm[rg][stream * DOUT + col0 + tx * 8];
            *(float4*)&qa[0] = *(const float4*)&qp[0];
            *(float4*)&qa[4] = *(const float4*)&qp[4];
#pragma unroll
            for (int jj = 0; jj < 8; jj++) {
                float d = qa[jj] - acc[ii][jj];
                s += d * d;
            }
        }
        part[ty * 8 + ii][tx] = s;
    }
    __syncthreads();
    if (tid < 128) {
        float tot = 0.f;
#pragma unroll
        for (int u = 0; u < 16; u++) tot += part[tid][u];
        int rg = row0 + tid;
        if (rg < QROWS) atomicAdd(&Dq[c][rg], tot);
    }
}

// ---------------- finalize ----------------
__global__ void final_kernel(float* __restrict__ out) {
    int idx = blockIdx.x * 256 + threadIdx.x;
    if (idx >= 500) return;
    int q = idx / 5, c = idx % 5;
    float s = 0.f;
    for (int t = 0; t < TT; t++) s += Dq[c][q * TT + t];
    out[idx] = -s / (float)TT;
}

// ---------------- launch ----------------
extern "C" void kernel_launch(void* const* d_in, const int* in_sizes, int n_in,
                              void* d_out, int out_size) {
    const float* sup = (const float*)d_in[0];
    const float* qry = (const float*)d_in[1];
    const int* labels = (const int*)d_in[2];
    const float* Wk  = (const float*)d_in[3];
    const float* bk  = (const float*)d_in[4];
    const float* Wv  = (const float*)d_in[5];
    const float* bv  = (const float*)d_in[6];
    const float* Wkl = (const float*)d_in[7];
    const float* bkl = (const float*)d_in[8];
    const float* Wvl = (const float*)d_in[9];
    const float* bvl = (const float*)d_in[10];
    const float* lng = (const float*)d_in[11];
    const float* lnb = (const float*)d_in[12];
    float* out = (float*)d_out;

    int ztot = Z0 + Z1 + Z2 + Z3 + Z4;
    zero_kernel<<<(ztot + 255) / 256, 256>>>();
    prep_kernel<<<(1000 * DIN) / 256, 256>>>(sup, qry);
    gemm_proj<<<dim3(9, 8, 12), 256>>>(Wk, Wv, Wkl, Wvl);
    combine_kernel<<<dim3(NB * TT, 4), 128>>>(bk, bv, bkl, bvl, lng, lnb, labels);
    gemm_scores<<<dim3(3, 44, 10), 256>>>();
    softmax_kernel<<<(10 * QROWS) / 8, 256>>>();
    gemm_av<<<dim3(9, 44, 10), 256>>>();
    final_kernel<<<2, 256>>>(out);
}